// round 5
// baseline (speedup 1.0000x reference)
#include <cuda_runtime.h>

// ---------------------------------------------------------------------------
// 2-layer GCN:  out = gcn(relu(gcn(x, W1, b1)), W2, b2)
// gcn(x,W,b)[v] = dis[v] * ( hs[v] + sum_{e: src->v} hs[src] ) + b
//   where hs = (x @ W) * dis[row],  dis[v] = rsqrt(1 + indeg(v))
// Strategy: per-launch CSR build (histogram + scan + fill), fp32 tiled SGEMMs
// with fused row scaling, pull-based warp-per-node aggregation (no fp atomics).
// ---------------------------------------------------------------------------

#define NNODES 100000
#define NEDGES 1600000
#define INC 128
#define HIDC 128
#define OUTC 64

// -------------------- scratch (device globals; no runtime alloc) -----------
__device__ int   g_cnt[NNODES];
__device__ int   g_cursor[NNODES];
__device__ int   g_rowptr[NNODES + 1];
__device__ int   g_partial[1024];
__device__ int   g_csr[NEDGES];
__device__ float g_dis[NNODES];
__device__ float g_hs1[(size_t)NNODES * HIDC];   // (x@W1)*dis
__device__ float g_x2 [(size_t)NNODES * HIDC];   // relu(layer1 out)
__device__ float g_hs2[(size_t)NNODES * OUTC];   // (x2@W2)*dis

// -------------------- CSR build --------------------------------------------
__global__ void k_init(int n) {
    int v = blockIdx.x * blockDim.x + threadIdx.x;
    if (v < n) { g_cnt[v] = 0; g_cursor[v] = 0; }
}

__global__ void k_count(const int* __restrict__ dst, int e) {
    int i = blockIdx.x * blockDim.x + threadIdx.x;
    if (i < e) atomicAdd(&g_cnt[dst[i]], 1);   // -> RED.ADD.U32
}

__global__ void k_dis(int n) {
    int v = blockIdx.x * blockDim.x + threadIdx.x;
    if (v < n) g_dis[v] = rsqrtf((float)(g_cnt[v] + 1));  // +1 self loop
}

// block-local exclusive scan (256/block) + block totals
__global__ void k_scan_blocks(int n) {
    __shared__ int warpsum[8];
    int idx  = blockIdx.x * 256 + threadIdx.x;
    int lane = threadIdx.x & 31;
    int w    = threadIdx.x >> 5;
    int x    = (idx < n) ? g_cnt[idx] : 0;
    int incl = x;
    #pragma unroll
    for (int o = 1; o < 32; o <<= 1) {
        int t = __shfl_up_sync(0xffffffffu, incl, o);
        if (lane >= o) incl += t;
    }
    if (lane == 31) warpsum[w] = incl;
    __syncthreads();
    if (w == 0) {
        int s = (lane < 8) ? warpsum[lane] : 0;
        #pragma unroll
        for (int o = 1; o < 8; o <<= 1) {
            int t = __shfl_up_sync(0xffffffffu, s, o);
            if (lane >= o) s += t;
        }
        if (lane < 8) warpsum[lane] = s;
    }
    __syncthreads();
    if (w > 0) incl += warpsum[w - 1];
    if (idx < n) g_rowptr[idx] = incl - x;            // block-local exclusive
    if (threadIdx.x == 255) g_partial[blockIdx.x] = incl;  // block total
}

// single block scans the <=512 block totals (exclusive, in place)
__global__ void k_scan_partials(int nb, int n) {
    __shared__ int warpsum[16];
    int tid  = threadIdx.x;
    int lane = tid & 31;
    int w    = tid >> 5;
    int x    = (tid < nb) ? g_partial[tid] : 0;
    int incl = x;
    #pragma unroll
    for (int o = 1; o < 32; o <<= 1) {
        int t = __shfl_up_sync(0xffffffffu, incl, o);
        if (lane >= o) incl += t;
    }
    if (lane == 31) warpsum[w] = incl;
    __syncthreads();
    if (w == 0) {
        int s = (lane < 16) ? warpsum[lane] : 0;
        #pragma unroll
        for (int o = 1; o < 16; o <<= 1) {
            int t = __shfl_up_sync(0xffffffffu, s, o);
            if (lane >= o) s += t;
        }
        if (lane < 16) warpsum[lane] = s;
    }
    __syncthreads();
    if (w > 0) incl += warpsum[w - 1];
    if (tid < nb) g_partial[tid] = incl - x;          // exclusive
    if (tid == nb - 1) g_rowptr[n] = incl;            // = total edge count
}

__global__ void k_add_offsets(int n) {
    int idx = blockIdx.x * 256 + threadIdx.x;
    if (idx < n) g_rowptr[idx] += g_partial[blockIdx.x];
}

__global__ void k_fill(const int* __restrict__ src, const int* __restrict__ dst, int e) {
    int i = blockIdx.x * blockDim.x + threadIdx.x;
    if (i < e) {
        int d = dst[i];
        int p = atomicAdd(&g_cursor[d], 1);
        g_csr[g_rowptr[d] + p] = src[i];
    }
}

// -------------------- GEMM 1: hs1 = (X @ W1) * dis[row] --------------------
// M x 128 x 128, BM=64 BN=128 BK=32, 256 threads, 8x4 micro-tile
__global__ void k_gemm1(const float* __restrict__ X, const float* __restrict__ W,
                        int m) {
    __shared__ __align__(16) float As[32][64];
    __shared__ __align__(16) float Bs[32][128];
    const int tid = threadIdx.x;
    const int tx  = tid & 31;   // col group: cols tx*4 .. tx*4+3
    const int ty  = tid >> 5;   // row group: rows ty*8 .. ty*8+7
    const int bm  = blockIdx.x * 64;

    float acc[8][4];
    #pragma unroll
    for (int r = 0; r < 8; r++)
        #pragma unroll
        for (int c = 0; c < 4; c++) acc[r][c] = 0.f;

    for (int k0 = 0; k0 < 128; k0 += 32) {
        // A tile: 64 rows x 32 k  (store transposed As[k][row])
        #pragma unroll
        for (int i = 0; i < 2; i++) {
            int idx = tid + i * 256;          // 0..511 float4s
            int r   = idx >> 3;               // 0..63
            int kq  = (idx & 7) * 4;          // 0..28
            float4 v = make_float4(0.f, 0.f, 0.f, 0.f);
            int grow = bm + r;
            if (grow < m)
                v = *(const float4*)(X + (size_t)grow * 128 + k0 + kq);
            As[kq + 0][r] = v.x; As[kq + 1][r] = v.y;
            As[kq + 2][r] = v.z; As[kq + 3][r] = v.w;
        }
        // B tile: 32 k x 128 n
        #pragma unroll
        for (int i = 0; i < 4; i++) {
            int idx = tid + i * 256;          // 0..1023 float4s
            int kr  = idx >> 5;               // 0..31
            int nq  = (idx & 31) * 4;         // 0..124
            *(float4*)&Bs[kr][nq] = *(const float4*)(W + (size_t)(k0 + kr) * 128 + nq);
        }
        __syncthreads();
        #pragma unroll
        for (int kk = 0; kk < 32; kk++) {
            float4 a0 = *(const float4*)&As[kk][ty * 8];
            float4 a1 = *(const float4*)&As[kk][ty * 8 + 4];
            float4 b  = *(const float4*)&Bs[kk][tx * 4];
            float ar[8] = {a0.x, a0.y, a0.z, a0.w, a1.x, a1.y, a1.z, a1.w};
            float br[4] = {b.x, b.y, b.z, b.w};
            #pragma unroll
            for (int r = 0; r < 8; r++)
                #pragma unroll
                for (int c = 0; c < 4; c++)
                    acc[r][c] = fmaf(ar[r], br[c], acc[r][c]);
        }
        __syncthreads();
    }
    #pragma unroll
    for (int r = 0; r < 8; r++) {
        int grow = bm + ty * 8 + r;
        if (grow < m) {
            float dv = g_dis[grow];
            float4 o = make_float4(acc[r][0] * dv, acc[r][1] * dv,
                                   acc[r][2] * dv, acc[r][3] * dv);
            *(float4*)(g_hs1 + (size_t)grow * 128 + tx * 4) = o;
        }
    }
}

// -------------------- Aggregation 1: x2 = relu(dis*(hs1[v]+sum)+b1) --------
__global__ void k_agg1(const float* __restrict__ b1, int n) {
    int v = (blockIdx.x * blockDim.x + threadIdx.x) >> 5;
    if (v >= n) return;
    int lane = threadIdx.x & 31;
    int c = lane * 4;
    int s0 = g_rowptr[v], s1 = g_rowptr[v + 1];
    float4 acc = *(const float4*)(g_hs1 + (size_t)v * 128 + c);  // self term
    for (int j = s0; j < s1; j += 32) {
        int mm = s1 - j; if (mm > 32) mm = 32;
        int sv = (lane < mm) ? g_csr[j + lane] : 0;
        for (int t = 0; t < mm; ++t) {
            int s = __shfl_sync(0xffffffffu, sv, t);
            float4 hv = *(const float4*)(g_hs1 + (size_t)s * 128 + c);
            acc.x += hv.x; acc.y += hv.y; acc.z += hv.z; acc.w += hv.w;
        }
    }
    float dv = g_dis[v];
    float4 bb = *(const float4*)(b1 + c);
    float4 o;
    o.x = fmaxf(fmaf(dv, acc.x, bb.x), 0.f);
    o.y = fmaxf(fmaf(dv, acc.y, bb.y), 0.f);
    o.z = fmaxf(fmaf(dv, acc.z, bb.z), 0.f);
    o.w = fmaxf(fmaf(dv, acc.w, bb.w), 0.f);
    *(float4*)(g_x2 + (size_t)v * 128 + c) = o;
}

// -------------------- GEMM 2: hs2 = (x2 @ W2) * dis[row] -------------------
// M x 64 x 128, BM=128 BN=64 BK=32, 256 threads, 8x4 micro-tile
__global__ void k_gemm2(const float* __restrict__ W, int m) {
    __shared__ __align__(16) float As[32][128];
    __shared__ __align__(16) float Bs[32][64];
    const int tid = threadIdx.x;
    const int tx  = tid & 15;   // cols tx*4 .. +3 (of 64)
    const int ty  = tid >> 4;   // rows ty*8 .. +7 (of 128)
    const int bm  = blockIdx.x * 128;

    float acc[8][4];
    #pragma unroll
    for (int r = 0; r < 8; r++)
        #pragma unroll
        for (int c = 0; c < 4; c++) acc[r][c] = 0.f;

    for (int k0 = 0; k0 < 128; k0 += 32) {
        // A tile: 128 rows x 32 k
        #pragma unroll
        for (int i = 0; i < 4; i++) {
            int idx = tid + i * 256;          // 0..1023 float4s
            int r   = idx >> 3;               // 0..127
            int kq  = (idx & 7) * 4;
            float4 v = make_float4(0.f, 0.f, 0.f, 0.f);
            int grow = bm + r;
            if (grow < m)
                v = *(const float4*)(g_x2 + (size_t)grow * 128 + k0 + kq);
            As[kq + 0][r] = v.x; As[kq + 1][r] = v.y;
            As[kq + 2][r] = v.z; As[kq + 3][r] = v.w;
        }
        // B tile: 32 k x 64 n
        #pragma unroll
        for (int i = 0; i < 2; i++) {
            int idx = tid + i * 256;          // 0..511 float4s
            int kr  = idx >> 4;               // 0..31
            int nq  = (idx & 15) * 4;         // 0..60
            *(float4*)&Bs[kr][nq] = *(const float4*)(W + (size_t)(k0 + kr) * 64 + nq);
        }
        __syncthreads();
        #pragma unroll
        for (int kk = 0; kk < 32; kk++) {
            float4 a0 = *(const float4*)&As[kk][ty * 8];
            float4 a1 = *(const float4*)&As[kk][ty * 8 + 4];
            float4 b  = *(const float4*)&Bs[kk][tx * 4];
            float ar[8] = {a0.x, a0.y, a0.z, a0.w, a1.x, a1.y, a1.z, a1.w};
            float br[4] = {b.x, b.y, b.z, b.w};
            #pragma unroll
            for (int r = 0; r < 8; r++)
                #pragma unroll
                for (int c = 0; c < 4; c++)
                    acc[r][c] = fmaf(ar[r], br[c], acc[r][c]);
        }
        __syncthreads();
    }
    #pragma unroll
    for (int r = 0; r < 8; r++) {
        int grow = bm + ty * 8 + r;
        if (grow < m) {
            float dv = g_dis[grow];
            float4 o = make_float4(acc[r][0] * dv, acc[r][1] * dv,
                                   acc[r][2] * dv, acc[r][3] * dv);
            *(float4*)(g_hs2 + (size_t)grow * 64 + tx * 4) = o;
        }
    }
}

// -------------------- Aggregation 2: out = dis*(hs2[v]+sum)+b2 -------------
__global__ void k_agg2(const float* __restrict__ b2, float* __restrict__ out, int n) {
    int v = (blockIdx.x * blockDim.x + threadIdx.x) >> 5;
    if (v >= n) return;
    int lane = threadIdx.x & 31;
    int c = lane * 2;
    int s0 = g_rowptr[v], s1 = g_rowptr[v + 1];
    float2 acc = *(const float2*)(g_hs2 + (size_t)v * 64 + c);   // self term
    for (int j = s0; j < s1; j += 32) {
        int mm = s1 - j; if (mm > 32) mm = 32;
        int sv = (lane < mm) ? g_csr[j + lane] : 0;
        for (int t = 0; t < mm; ++t) {
            int s = __shfl_sync(0xffffffffu, sv, t);
            float2 hv = *(const float2*)(g_hs2 + (size_t)s * 64 + c);
            acc.x += hv.x; acc.y += hv.y;
        }
    }
    float dv = g_dis[v];
    float2 bb = *(const float2*)(b2 + c);
    float2 o;
    o.x = fmaf(dv, acc.x, bb.x);
    o.y = fmaf(dv, acc.y, bb.y);
    *(float2*)(out + (size_t)v * 64 + c) = o;
}

// -------------------- launch ------------------------------------------------
extern "C" void kernel_launch(void* const* d_in, const int* in_sizes, int n_in,
                              void* d_out, int out_size) {
    const float* x  = (const float*)d_in[0];
    const int*   ei = (const int*)d_in[1];
    const float* W1 = (const float*)d_in[2];
    const float* b1 = (const float*)d_in[3];
    const float* W2 = (const float*)d_in[4];
    const float* b2 = (const float*)d_in[5];
    float* out = (float*)d_out;

    const int n = in_sizes[0] / INC;   // 100000
    const int e = in_sizes[1] / 2;     // 1600000
    const int* src = ei;
    const int* dst = ei + e;

    const int nb_n = (n + 255) / 256;  // 391
    const int nb_e = (e + 255) / 256;

    // CSR build + normalization
    k_init<<<nb_n, 256>>>(n);
    k_count<<<nb_e, 256>>>(dst, e);
    k_dis<<<nb_n, 256>>>(n);
    k_scan_blocks<<<nb_n, 256>>>(n);
    k_scan_partials<<<1, 512>>>(nb_n, n);
    k_add_offsets<<<nb_n, 256>>>(n);
    k_fill<<<nb_e, 256>>>(src, dst, e);

    // Layer 1
    k_gemm1<<<(n + 63) / 64, 256>>>(x, W1, n);
    k_agg1<<<(n + 7) / 8, 256>>>(b1, n);

    // Layer 2
    k_gemm2<<<(n + 127) / 128, 256>>>(W2, n);
    k_agg2<<<(n + 7) / 8, 256>>>(b2, out, n);
}

// round 7
// speedup vs baseline: 1.2894x; 1.2894x over previous
#include <cuda_runtime.h>
#include <cstdint>

// ---------------------------------------------------------------------------
// 2-layer GCN:  out = gcn(relu(gcn(x, W1, b1)), W2, b2)
// gcn(x,W,b)[v] = dis[v] * ( hs[v] + sum_{e: src->v} hs[src] ) + b
//   hs = (x @ W) * dis[row],  dis[v] = rsqrt(1 + indeg(v))
// GEMMs: tf32 mma.sync (m16n8k8) — legal at PTX target sm_100 (tcgen05 is not).
// Aggregation: pull-based CSR gather (no fp atomics).
// ---------------------------------------------------------------------------

#define NNODES 100000
#define NEDGES 1600000
#define INC 128
#define HIDC 128
#define OUTC 64

// -------------------- scratch (device globals; no runtime alloc) -----------
__device__ int   g_cnt[NNODES];
__device__ int   g_cursor[NNODES];
__device__ int   g_rowptr[NNODES + 1];
__device__ int   g_partial[1024];
__device__ int   g_csr[NEDGES];
__device__ float g_dis[NNODES];
__device__ float g_hs1[(size_t)NNODES * HIDC];   // (x@W1)*dis
__device__ float g_x2 [(size_t)NNODES * HIDC];   // relu(layer1 out)
__device__ float g_hs2[(size_t)NNODES * OUTC];   // (x2@W2)*dis

// -------------------- helpers ----------------------------------------------
__device__ __forceinline__ uint32_t f2tf32(float v) {
    uint32_t u;
    asm("cvt.rna.tf32.f32 %0, %1;" : "=r"(u) : "f"(v));
    return u;
}

__device__ __forceinline__ void mma_tf32(float* c, const uint32_t* a,
                                         uint32_t b0, uint32_t b1) {
    asm volatile(
        "mma.sync.aligned.m16n8k8.row.col.f32.tf32.tf32.f32 "
        "{%0,%1,%2,%3}, {%4,%5,%6,%7}, {%8,%9}, {%0,%1,%2,%3};"
        : "+f"(c[0]), "+f"(c[1]), "+f"(c[2]), "+f"(c[3])
        : "r"(a[0]), "r"(a[1]), "r"(a[2]), "r"(a[3]), "r"(b0), "r"(b1));
}

// -------------------- CSR build --------------------------------------------
__global__ void k_init(int n) {
    int v = blockIdx.x * blockDim.x + threadIdx.x;
    if (v < n) { g_cnt[v] = 0; g_cursor[v] = 0; }
}

__global__ void k_count(const int* __restrict__ dst, int e) {
    int i = blockIdx.x * blockDim.x + threadIdx.x;
    if (i < e) atomicAdd(&g_cnt[dst[i]], 1);
}

__global__ void k_dis(int n) {
    int v = blockIdx.x * blockDim.x + threadIdx.x;
    if (v < n) g_dis[v] = rsqrtf((float)(g_cnt[v] + 1));
}

__global__ void k_scan_blocks(int n) {
    __shared__ int warpsum[8];
    int idx  = blockIdx.x * 256 + threadIdx.x;
    int lane = threadIdx.x & 31;
    int w    = threadIdx.x >> 5;
    int x    = (idx < n) ? g_cnt[idx] : 0;
    int incl = x;
    #pragma unroll
    for (int o = 1; o < 32; o <<= 1) {
        int t = __shfl_up_sync(0xffffffffu, incl, o);
        if (lane >= o) incl += t;
    }
    if (lane == 31) warpsum[w] = incl;
    __syncthreads();
    if (w == 0) {
        int s = (lane < 8) ? warpsum[lane] : 0;
        #pragma unroll
        for (int o = 1; o < 8; o <<= 1) {
            int t = __shfl_up_sync(0xffffffffu, s, o);
            if (lane >= o) s += t;
        }
        if (lane < 8) warpsum[lane] = s;
    }
    __syncthreads();
    if (w > 0) incl += warpsum[w - 1];
    if (idx < n) g_rowptr[idx] = incl - x;
    if (threadIdx.x == 255) g_partial[blockIdx.x] = incl;
}

__global__ void k_scan_partials(int nb, int n) {
    __shared__ int warpsum[16];
    int tid  = threadIdx.x;
    int lane = tid & 31;
    int w    = tid >> 5;
    int x    = (tid < nb) ? g_partial[tid] : 0;
    int incl = x;
    #pragma unroll
    for (int o = 1; o < 32; o <<= 1) {
        int t = __shfl_up_sync(0xffffffffu, incl, o);
        if (lane >= o) incl += t;
    }
    if (lane == 31) warpsum[w] = incl;
    __syncthreads();
    if (w == 0) {
        int s = (lane < 16) ? warpsum[lane] : 0;
        #pragma unroll
        for (int o = 1; o < 16; o <<= 1) {
            int t = __shfl_up_sync(0xffffffffu, s, o);
            if (lane >= o) s += t;
        }
        if (lane < 16) warpsum[lane] = s;
    }
    __syncthreads();
    if (w > 0) incl += warpsum[w - 1];
    if (tid < nb) g_partial[tid] = incl - x;
    if (tid == nb - 1) g_rowptr[n] = incl;
}

__global__ void k_add_offsets(int n) {
    int idx = blockIdx.x * 256 + threadIdx.x;
    if (idx < n) g_rowptr[idx] += g_partial[blockIdx.x];
}

__global__ void k_fill(const int* __restrict__ src, const int* __restrict__ dst, int e) {
    int i = blockIdx.x * blockDim.x + threadIdx.x;
    if (i < e) {
        int d = dst[i];
        int p = atomicAdd(&g_cursor[d], 1);
        g_csr[g_rowptr[d] + p] = src[i];
    }
}

// -------------------- GEMM 1 (tf32 mma.sync): hs1 = (X @ W1) * dis ---------
// CTA: 128 rows x 128 cols, full K=128 in SMEM. 8 warps: warp = 32m x 64n.
// As stride 132 (A-frag banks 4r+c distinct), Bs stride 136 (banks 8k+n distinct).
#define AS_STRIDE 132
#define BS1_STRIDE 136
#define G1_SMEM ((128 * AS_STRIDE + 128 * BS1_STRIDE) * 4)

__global__ void __launch_bounds__(256)
k_gemm1_mma(const float* __restrict__ X, const float* __restrict__ W, int m) {
    extern __shared__ uint32_t sm[];
    uint32_t* As = sm;                       // [128][132] tf32 bits
    uint32_t* Bs = sm + 128 * AS_STRIDE;     // [128][136] tf32 bits
    const int tid  = threadIdx.x;
    const int lane = tid & 31;
    const int wid  = tid >> 5;
    const int gr   = lane >> 2;              // group row 0..7
    const int gc   = lane & 3;               // group col 0..3
    const int bm   = blockIdx.x * 128;
    const int m0   = (wid & 3) * 32;
    const int n0   = (wid >> 2) * 64;

    // load A = X tile (tf32 rounded)
    #pragma unroll
    for (int i = 0; i < 16; i++) {
        int f = tid + i * 256;               // 0..4095 float4
        int r = f >> 5, c4 = (f & 31) * 4;
        float4 v = make_float4(0.f, 0.f, 0.f, 0.f);
        if (bm + r < m) v = *(const float4*)(X + (size_t)(bm + r) * 128 + c4);
        uint32_t* p = As + r * AS_STRIDE + c4;
        p[0] = f2tf32(v.x); p[1] = f2tf32(v.y); p[2] = f2tf32(v.z); p[3] = f2tf32(v.w);
    }
    // load B = W1 [k][n] (row-major == mma B layout)
    #pragma unroll
    for (int i = 0; i < 16; i++) {
        int f = tid + i * 256;
        int r = f >> 5, c4 = (f & 31) * 4;
        float4 v = *(const float4*)(W + (size_t)r * 128 + c4);
        uint32_t* p = Bs + r * BS1_STRIDE + c4;
        p[0] = f2tf32(v.x); p[1] = f2tf32(v.y); p[2] = f2tf32(v.z); p[3] = f2tf32(v.w);
    }
    __syncthreads();

    float acc[2][8][4];
    #pragma unroll
    for (int a = 0; a < 2; a++)
        #pragma unroll
        for (int j = 0; j < 8; j++)
            #pragma unroll
            for (int q = 0; q < 4; q++) acc[a][j][q] = 0.f;

    #pragma unroll
    for (int k0 = 0; k0 < 128; k0 += 8) {
        uint32_t a[2][4];
        #pragma unroll
        for (int mf = 0; mf < 2; mf++) {
            int r = m0 + mf * 16 + gr;
            a[mf][0] = As[(r    ) * AS_STRIDE + k0 + gc    ];
            a[mf][1] = As[(r + 8) * AS_STRIDE + k0 + gc    ];
            a[mf][2] = As[(r    ) * AS_STRIDE + k0 + gc + 4];
            a[mf][3] = As[(r + 8) * AS_STRIDE + k0 + gc + 4];
        }
        #pragma unroll
        for (int j = 0; j < 8; j++) {
            int nn = n0 + j * 8 + gr;
            uint32_t b0 = Bs[(k0 + gc    ) * BS1_STRIDE + nn];
            uint32_t b1 = Bs[(k0 + gc + 4) * BS1_STRIDE + nn];
            mma_tf32(acc[0][j], a[0], b0, b1);
            mma_tf32(acc[1][j], a[1], b0, b1);
        }
    }

    // epilogue: *dis, write hs1
    #pragma unroll
    for (int mf = 0; mf < 2; mf++) {
        int r0 = bm + m0 + mf * 16 + gr;
        int r1 = r0 + 8;
        float d0 = (r0 < m) ? g_dis[r0] : 0.f;
        float d1 = (r1 < m) ? g_dis[r1] : 0.f;
        #pragma unroll
        for (int j = 0; j < 8; j++) {
            int col = n0 + j * 8 + gc * 2;
            if (r0 < m)
                *(float2*)(g_hs1 + (size_t)r0 * 128 + col) =
                    make_float2(acc[mf][j][0] * d0, acc[mf][j][1] * d0);
            if (r1 < m)
                *(float2*)(g_hs1 + (size_t)r1 * 128 + col) =
                    make_float2(acc[mf][j][2] * d1, acc[mf][j][3] * d1);
        }
    }
}

// -------------------- GEMM 2 (tf32 mma.sync): hs2 = (x2 @ W2) * dis --------
// CTA: 128 rows x 64 cols. 8 warps: warp = 32m x 32n. Bs stride 72.
#define BS2_STRIDE 72
#define G2_SMEM ((128 * AS_STRIDE + 128 * BS2_STRIDE) * 4)

__global__ void __launch_bounds__(256)
k_gemm2_mma(const float* __restrict__ W, int m) {
    extern __shared__ uint32_t sm[];
    uint32_t* As = sm;                       // [128][132]
    uint32_t* Bs = sm + 128 * AS_STRIDE;     // [128][72]
    const int tid  = threadIdx.x;
    const int lane = tid & 31;
    const int wid  = tid >> 5;
    const int gr   = lane >> 2;
    const int gc   = lane & 3;
    const int bm   = blockIdx.x * 128;
    const int m0   = (wid & 3) * 32;
    const int n0   = (wid >> 2) * 32;

    #pragma unroll
    for (int i = 0; i < 16; i++) {
        int f = tid + i * 256;
        int r = f >> 5, c4 = (f & 31) * 4;
        float4 v = make_float4(0.f, 0.f, 0.f, 0.f);
        if (bm + r < m) v = *(const float4*)(g_x2 + (size_t)(bm + r) * 128 + c4);
        uint32_t* p = As + r * AS_STRIDE + c4;
        p[0] = f2tf32(v.x); p[1] = f2tf32(v.y); p[2] = f2tf32(v.z); p[3] = f2tf32(v.w);
    }
    #pragma unroll
    for (int i = 0; i < 8; i++) {
        int f = tid + i * 256;               // 0..2047 float4
        int r = f >> 4, c4 = (f & 15) * 4;
        float4 v = *(const float4*)(W + (size_t)r * 64 + c4);
        uint32_t* p = Bs + r * BS2_STRIDE + c4;
        p[0] = f2tf32(v.x); p[1] = f2tf32(v.y); p[2] = f2tf32(v.z); p[3] = f2tf32(v.w);
    }
    __syncthreads();

    float acc[2][4][4];
    #pragma unroll
    for (int a = 0; a < 2; a++)
        #pragma unroll
        for (int j = 0; j < 4; j++)
            #pragma unroll
            for (int q = 0; q < 4; q++) acc[a][j][q] = 0.f;

    #pragma unroll
    for (int k0 = 0; k0 < 128; k0 += 8) {
        uint32_t a[2][4];
        #pragma unroll
        for (int mf = 0; mf < 2; mf++) {
            int r = m0 + mf * 16 + gr;
            a[mf][0] = As[(r    ) * AS_STRIDE + k0 + gc    ];
            a[mf][1] = As[(r + 8) * AS_STRIDE + k0 + gc    ];
            a[mf][2] = As[(r    ) * AS_STRIDE + k0 + gc + 4];
            a[mf][3] = As[(r + 8) * AS_STRIDE + k0 + gc + 4];
        }
        #pragma unroll
        for (int j = 0; j < 4; j++) {
            int nn = n0 + j * 8 + gr;
            uint32_t b0 = Bs[(k0 + gc    ) * BS2_STRIDE + nn];
            uint32_t b1 = Bs[(k0 + gc + 4) * BS2_STRIDE + nn];
            mma_tf32(acc[0][j], a[0], b0, b1);
            mma_tf32(acc[1][j], a[1], b0, b1);
        }
    }

    #pragma unroll
    for (int mf = 0; mf < 2; mf++) {
        int r0 = bm + m0 + mf * 16 + gr;
        int r1 = r0 + 8;
        float d0 = (r0 < m) ? g_dis[r0] : 0.f;
        float d1 = (r1 < m) ? g_dis[r1] : 0.f;
        #pragma unroll
        for (int j = 0; j < 4; j++) {
            int col = n0 + j * 8 + gc * 2;
            if (r0 < m)
                *(float2*)(g_hs2 + (size_t)r0 * 64 + col) =
                    make_float2(acc[mf][j][0] * d0, acc[mf][j][1] * d0);
            if (r1 < m)
                *(float2*)(g_hs2 + (size_t)r1 * 64 + col) =
                    make_float2(acc[mf][j][2] * d1, acc[mf][j][3] * d1);
        }
    }
}

// -------------------- Aggregation 1: x2 = relu(dis*(hs1[v]+sum)+b1) --------
__global__ void k_agg1(const float* __restrict__ b1, int n) {
    int v = (blockIdx.x * blockDim.x + threadIdx.x) >> 5;
    if (v >= n) return;
    int lane = threadIdx.x & 31;
    int c = lane * 4;
    int s0 = g_rowptr[v], s1 = g_rowptr[v + 1];
    float4 acc = *(const float4*)(g_hs1 + (size_t)v * 128 + c);
    for (int j = s0; j < s1; j += 32) {
        int mm = s1 - j; if (mm > 32) mm = 32;
        int sv = (lane < mm) ? g_csr[j + lane] : 0;
        for (int t = 0; t < mm; ++t) {
            int s = __shfl_sync(0xffffffffu, sv, t);
            float4 hv = *(const float4*)(g_hs1 + (size_t)s * 128 + c);
            acc.x += hv.x; acc.y += hv.y; acc.z += hv.z; acc.w += hv.w;
        }
    }
    float dv = g_dis[v];
    float4 bb = *(const float4*)(b1 + c);
    float4 o;
    o.x = fmaxf(fmaf(dv, acc.x, bb.x), 0.f);
    o.y = fmaxf(fmaf(dv, acc.y, bb.y), 0.f);
    o.z = fmaxf(fmaf(dv, acc.z, bb.z), 0.f);
    o.w = fmaxf(fmaf(dv, acc.w, bb.w), 0.f);
    *(float4*)(g_x2 + (size_t)v * 128 + c) = o;
}

// -------------------- Aggregation 2: out = dis*(hs2[v]+sum)+b2 -------------
__global__ void k_agg2(const float* __restrict__ b2, float* __restrict__ out, int n) {
    int v = (blockIdx.x * blockDim.x + threadIdx.x) >> 5;
    if (v >= n) return;
    int lane = threadIdx.x & 31;
    int c = lane * 2;
    int s0 = g_rowptr[v], s1 = g_rowptr[v + 1];
    float2 acc = *(const float2*)(g_hs2 + (size_t)v * 64 + c);
    for (int j = s0; j < s1; j += 32) {
        int mm = s1 - j; if (mm > 32) mm = 32;
        int sv = (lane < mm) ? g_csr[j + lane] : 0;
        for (int t = 0; t < mm; ++t) {
            int s = __shfl_sync(0xffffffffu, sv, t);
            float2 hv = *(const float2*)(g_hs2 + (size_t)s * 64 + c);
            acc.x += hv.x; acc.y += hv.y;
        }
    }
    float dv = g_dis[v];
    float2 bb = *(const float2*)(b2 + c);
    float2 o;
    o.x = fmaf(dv, acc.x, bb.x);
    o.y = fmaf(dv, acc.y, bb.y);
    *(float2*)(out + (size_t)v * 64 + c) = o;
}

// -------------------- launch ------------------------------------------------
extern "C" void kernel_launch(void* const* d_in, const int* in_sizes, int n_in,
                              void* d_out, int out_size) {
    const float* x  = (const float*)d_in[0];
    const int*   ei = (const int*)d_in[1];
    const float* W1 = (const float*)d_in[2];
    const float* b1 = (const float*)d_in[3];
    const float* W2 = (const float*)d_in[4];
    const float* b2 = (const float*)d_in[5];
    float* out = (float*)d_out;

    const int n = in_sizes[0] / INC;   // 100000
    const int e = in_sizes[1] / 2;     // 1600000
    const int* src = ei;
    const int* dst = ei + e;

    const int nb_n = (n + 255) / 256;
    const int nb_e = (e + 255) / 256;

    static bool attr_done = false;
    if (!attr_done) {
        cudaFuncSetAttribute(k_gemm1_mma,
                             cudaFuncAttributeMaxDynamicSharedMemorySize, G1_SMEM);
        cudaFuncSetAttribute(k_gemm2_mma,
                             cudaFuncAttributeMaxDynamicSharedMemorySize, G2_SMEM);
        attr_done = true;
    }

    // CSR build + normalization
    k_init<<<nb_n, 256>>>(n);
    k_count<<<nb_e, 256>>>(dst, e);
    k_dis<<<nb_n, 256>>>(n);
    k_scan_blocks<<<nb_n, 256>>>(n);
    k_scan_partials<<<1, 512>>>(nb_n, n);
    k_add_offsets<<<nb_n, 256>>>(n);
    k_fill<<<nb_e, 256>>>(src, dst, e);

    // Layer 1
    k_gemm1_mma<<<(n + 127) / 128, 256, G1_SMEM>>>(x, W1, n);
    k_agg1<<<(n + 7) / 8, 256>>>(b1, n);

    // Layer 2
    k_gemm2_mma<<<(n + 127) / 128, 256, G2_SMEM>>>(W2, n);
    k_agg2<<<(n + 7) / 8, 256>>>(b2, out, n);
}

// round 8
// speedup vs baseline: 1.3500x; 1.0470x over previous
#include <cuda_runtime.h>
#include <cuda_fp16.h>
#include <cstdint>

// ---------------------------------------------------------------------------
// 2-layer GCN:  out = gcn(relu(gcn(x, W1, b1)), W2, b2)
// gcn(x,W,b)[v] = dis[v] * ( hs[v] + sum_{e: src->v} hs[src] ) + b
//   hs = (x @ W) * dis[row],  dis[v] = rsqrt(1 + indeg(v))
// GEMMs: tf32 mma.sync (m16n8k8). hs buffers stored fp16 (fp32 accumulation)
// to halve the L2 gather traffic. CSR build fused into one kernel with a
// software grid barrier. Aggregation: pull-based CSR gather (no fp atomics).
// ---------------------------------------------------------------------------

#define NNODES 100000
#define NEDGES 1600000
#define INC 128
#define HIDC 128
#define OUTC 64

// -------------------- scratch (device globals; no runtime alloc) -----------
__device__ int   g_cnt[NNODES];
__device__ int   g_cursor[NNODES];
__device__ int   g_rowptr[NNODES + 1];
__device__ int   g_partial[1024];
__device__ int   g_csr[NEDGES];
__device__ float g_dis[NNODES];
__device__ __half g_hs1[(size_t)NNODES * HIDC];  // (x@W1)*dis   (fp16)
__device__ float  g_x2 [(size_t)NNODES * HIDC];  // relu(layer1 out)
__device__ __half g_hs2[(size_t)NNODES * OUTC];  // (x2@W2)*dis  (fp16)
__device__ int   g_bar_cnt;   // software grid barrier state
__device__ int   g_bar_gen;

// -------------------- helpers ----------------------------------------------
__device__ __forceinline__ uint32_t f2tf32(float v) {
    uint32_t u;
    asm("cvt.rna.tf32.f32 %0, %1;" : "=r"(u) : "f"(v));
    return u;
}

__device__ __forceinline__ void mma_tf32(float* c, const uint32_t* a,
                                         uint32_t b0, uint32_t b1) {
    asm volatile(
        "mma.sync.aligned.m16n8k8.row.col.f32.tf32.tf32.f32 "
        "{%0,%1,%2,%3}, {%4,%5,%6,%7}, {%8,%9}, {%0,%1,%2,%3};"
        : "+f"(c[0]), "+f"(c[1]), "+f"(c[2]), "+f"(c[3])
        : "r"(a[0]), "r"(a[1]), "r"(a[2]), "r"(a[3]), "r"(b0), "r"(b1));
}

// software grid barrier: valid only when all nb CTAs are co-resident.
__device__ __forceinline__ void gbar(int nb) {
    __syncthreads();
    if (threadIdx.x == 0) {
        __threadfence();
        int gen = atomicAdd(&g_bar_gen, 0);
        if (atomicAdd(&g_bar_cnt, 1) == nb - 1) {
            g_bar_cnt = 0;
            __threadfence();
            atomicAdd(&g_bar_gen, 1);
        } else {
            while (atomicAdd(&g_bar_gen, 0) == gen) {}
        }
    }
    __syncthreads();
}

// -------------------- fused CSR build (one kernel, 6 phases) ---------------
// grid = NB = ceil(n/256) = 391 CTAs of 256 threads — all co-resident
// (148 SMs x >=4 CTA capacity at these resources).
__global__ void __launch_bounds__(256)
k_csr(const int* __restrict__ src, const int* __restrict__ dst,
      int n, int e, int nb) {
    __shared__ int warpsum[8];
    const int tid  = threadIdx.x;
    const int lane = tid & 31;
    const int w    = tid >> 5;
    const int idx  = blockIdx.x * 256 + tid;
    const int gstr = nb * 256;

    // P0: zero counts
    if (idx < n) g_cnt[idx] = 0;
    gbar(nb);

    // P1: in-degree histogram
    for (int i = blockIdx.x * 256 + tid; i < e; i += gstr)
        atomicAdd(&g_cnt[dst[i]], 1);
    gbar(nb);

    // P2: dis + block-local exclusive scan of counts
    {
        int x = (idx < n) ? g_cnt[idx] : 0;
        if (idx < n) g_dis[idx] = rsqrtf((float)(x + 1));
        int incl = x;
        #pragma unroll
        for (int o = 1; o < 32; o <<= 1) {
            int t = __shfl_up_sync(0xffffffffu, incl, o);
            if (lane >= o) incl += t;
        }
        if (lane == 31) warpsum[w] = incl;
        __syncthreads();
        if (w == 0) {
            int s = (lane < 8) ? warpsum[lane] : 0;
            #pragma unroll
            for (int o = 1; o < 8; o <<= 1) {
                int t = __shfl_up_sync(0xffffffffu, s, o);
                if (lane >= o) s += t;
            }
            if (lane < 8) warpsum[lane] = s;
        }
        __syncthreads();
        if (w > 0) incl += warpsum[w - 1];
        if (idx < n) g_rowptr[idx] = incl - x;
        if (tid == 255) g_partial[blockIdx.x] = incl;
    }
    gbar(nb);

    // P3: block 0 scans the nb block totals (2 elements per thread)
    if (blockIdx.x == 0) {
        int i0 = 2 * tid, i1 = 2 * tid + 1;
        int a = (i0 < nb) ? g_partial[i0] : 0;
        int b = (i1 < nb) ? g_partial[i1] : 0;
        int tot = a + b;
        int incl = tot;
        #pragma unroll
        for (int o = 1; o < 32; o <<= 1) {
            int t = __shfl_up_sync(0xffffffffu, incl, o);
            if (lane >= o) incl += t;
        }
        if (lane == 31) warpsum[w] = incl;
        __syncthreads();
        if (w == 0) {
            int s = (lane < 8) ? warpsum[lane] : 0;
            #pragma unroll
            for (int o = 1; o < 8; o <<= 1) {
                int t = __shfl_up_sync(0xffffffffu, s, o);
                if (lane >= o) s += t;
            }
            if (lane < 8) warpsum[lane] = s;
        }
        __syncthreads();
        if (w > 0) incl += warpsum[w - 1];
        int excl = incl - tot;
        if (i0 < nb) g_partial[i0] = excl;
        if (i1 < nb) g_partial[i1] = excl + a;
        if (tid == 255) g_rowptr[n] = incl;   // total = e
    }
    gbar(nb);

    // P4: add block offsets; init fill cursor to absolute row start
    if (idx < n) {
        int v = g_rowptr[idx] + g_partial[blockIdx.x];
        g_rowptr[idx] = v;
        g_cursor[idx] = v;
    }
    gbar(nb);

    // P5: fill CSR adjacency
    for (int i = blockIdx.x * 256 + tid; i < e; i += gstr) {
        int d = dst[i];
        int p = atomicAdd(&g_cursor[d], 1);
        g_csr[p] = src[i];
    }
}

// -------------------- GEMM 1 (tf32 mma.sync): hs1 = (X @ W1) * dis ---------
// CTA: 128 rows x 128 cols, full K=128 in SMEM. 8 warps: warp = 32m x 64n.
#define AS_STRIDE 132
#define BS1_STRIDE 136
#define G1_SMEM ((128 * AS_STRIDE + 128 * BS1_STRIDE) * 4)

__global__ void __launch_bounds__(256)
k_gemm1_mma(const float* __restrict__ X, const float* __restrict__ W, int m) {
    extern __shared__ uint32_t sm[];
    uint32_t* As = sm;                       // [128][132] tf32 bits
    uint32_t* Bs = sm + 128 * AS_STRIDE;     // [128][136] tf32 bits
    const int tid  = threadIdx.x;
    const int lane = tid & 31;
    const int wid  = tid >> 5;
    const int gr   = lane >> 2;
    const int gc   = lane & 3;
    const int bm   = blockIdx.x * 128;
    const int m0   = (wid & 3) * 32;
    const int n0   = (wid >> 2) * 64;

    #pragma unroll
    for (int i = 0; i < 16; i++) {
        int f = tid + i * 256;
        int r = f >> 5, c4 = (f & 31) * 4;
        float4 v = make_float4(0.f, 0.f, 0.f, 0.f);
        if (bm + r < m) v = *(const float4*)(X + (size_t)(bm + r) * 128 + c4);
        uint32_t* p = As + r * AS_STRIDE + c4;
        p[0] = f2tf32(v.x); p[1] = f2tf32(v.y); p[2] = f2tf32(v.z); p[3] = f2tf32(v.w);
    }
    #pragma unroll
    for (int i = 0; i < 16; i++) {
        int f = tid + i * 256;
        int r = f >> 5, c4 = (f & 31) * 4;
        float4 v = *(const float4*)(W + (size_t)r * 128 + c4);
        uint32_t* p = Bs + r * BS1_STRIDE + c4;
        p[0] = f2tf32(v.x); p[1] = f2tf32(v.y); p[2] = f2tf32(v.z); p[3] = f2tf32(v.w);
    }
    __syncthreads();

    float acc[2][8][4];
    #pragma unroll
    for (int a = 0; a < 2; a++)
        #pragma unroll
        for (int j = 0; j < 8; j++)
            #pragma unroll
            for (int q = 0; q < 4; q++) acc[a][j][q] = 0.f;

    #pragma unroll
    for (int k0 = 0; k0 < 128; k0 += 8) {
        uint32_t a[2][4];
        #pragma unroll
        for (int mf = 0; mf < 2; mf++) {
            int r = m0 + mf * 16 + gr;
            a[mf][0] = As[(r    ) * AS_STRIDE + k0 + gc    ];
            a[mf][1] = As[(r + 8) * AS_STRIDE + k0 + gc    ];
            a[mf][2] = As[(r    ) * AS_STRIDE + k0 + gc + 4];
            a[mf][3] = As[(r + 8) * AS_STRIDE + k0 + gc + 4];
        }
        #pragma unroll
        for (int j = 0; j < 8; j++) {
            int nn = n0 + j * 8 + gr;
            uint32_t b0 = Bs[(k0 + gc    ) * BS1_STRIDE + nn];
            uint32_t b1 = Bs[(k0 + gc + 4) * BS1_STRIDE + nn];
            mma_tf32(acc[0][j], a[0], b0, b1);
            mma_tf32(acc[1][j], a[1], b0, b1);
        }
    }

    // epilogue: *dis, write hs1 as fp16
    #pragma unroll
    for (int mf = 0; mf < 2; mf++) {
        int r0 = bm + m0 + mf * 16 + gr;
        int r1 = r0 + 8;
        float d0 = (r0 < m) ? g_dis[r0] : 0.f;
        float d1 = (r1 < m) ? g_dis[r1] : 0.f;
        #pragma unroll
        for (int j = 0; j < 8; j++) {
            int col = n0 + j * 8 + gc * 2;
            if (r0 < m)
                *(__half2*)(g_hs1 + (size_t)r0 * 128 + col) =
                    __floats2half2_rn(acc[mf][j][0] * d0, acc[mf][j][1] * d0);
            if (r1 < m)
                *(__half2*)(g_hs1 + (size_t)r1 * 128 + col) =
                    __floats2half2_rn(acc[mf][j][2] * d1, acc[mf][j][3] * d1);
        }
    }
}

// -------------------- GEMM 2 (tf32 mma.sync): hs2 = (x2 @ W2) * dis --------
#define BS2_STRIDE 72
#define G2_SMEM ((128 * AS_STRIDE + 128 * BS2_STRIDE) * 4)

__global__ void __launch_bounds__(256)
k_gemm2_mma(const float* __restrict__ W, int m) {
    extern __shared__ uint32_t sm[];
    uint32_t* As = sm;                       // [128][132]
    uint32_t* Bs = sm + 128 * AS_STRIDE;     // [128][72]
    const int tid  = threadIdx.x;
    const int lane = tid & 31;
    const int wid  = tid >> 5;
    const int gr   = lane >> 2;
    const int gc   = lane & 3;
    const int bm   = blockIdx.x * 128;
    const int m0   = (wid & 3) * 32;
    const int n0   = (wid >> 2) * 32;

    #pragma unroll
    for (int i = 0; i < 16; i++) {
        int f = tid + i * 256;
        int r = f >> 5, c4 = (f & 31) * 4;
        float4 v = make_float4(0.f, 0.f, 0.f, 0.f);
        if (bm + r < m) v = *(const float4*)(g_x2 + (size_t)(bm + r) * 128 + c4);
        uint32_t* p = As + r * AS_STRIDE + c4;
        p[0] = f2tf32(v.x); p[1] = f2tf32(v.y); p[2] = f2tf32(v.z); p[3] = f2tf32(v.w);
    }
    #pragma unroll
    for (int i = 0; i < 8; i++) {
        int f = tid + i * 256;
        int r = f >> 4, c4 = (f & 15) * 4;
        float4 v = *(const float4*)(W + (size_t)r * 64 + c4);
        uint32_t* p = Bs + r * BS2_STRIDE + c4;
        p[0] = f2tf32(v.x); p[1] = f2tf32(v.y); p[2] = f2tf32(v.z); p[3] = f2tf32(v.w);
    }
    __syncthreads();

    float acc[2][4][4];
    #pragma unroll
    for (int a = 0; a < 2; a++)
        #pragma unroll
        for (int j = 0; j < 4; j++)
            #pragma unroll
            for (int q = 0; q < 4; q++) acc[a][j][q] = 0.f;

    #pragma unroll
    for (int k0 = 0; k0 < 128; k0 += 8) {
        uint32_t a[2][4];
        #pragma unroll
        for (int mf = 0; mf < 2; mf++) {
            int r = m0 + mf * 16 + gr;
            a[mf][0] = As[(r    ) * AS_STRIDE + k0 + gc    ];
            a[mf][1] = As[(r + 8) * AS_STRIDE + k0 + gc    ];
            a[mf][2] = As[(r    ) * AS_STRIDE + k0 + gc + 4];
            a[mf][3] = As[(r + 8) * AS_STRIDE + k0 + gc + 4];
        }
        #pragma unroll
        for (int j = 0; j < 4; j++) {
            int nn = n0 + j * 8 + gr;
            uint32_t b0 = Bs[(k0 + gc    ) * BS2_STRIDE + nn];
            uint32_t b1 = Bs[(k0 + gc + 4) * BS2_STRIDE + nn];
            mma_tf32(acc[0][j], a[0], b0, b1);
            mma_tf32(acc[1][j], a[1], b0, b1);
        }
    }

    #pragma unroll
    for (int mf = 0; mf < 2; mf++) {
        int r0 = bm + m0 + mf * 16 + gr;
        int r1 = r0 + 8;
        float d0 = (r0 < m) ? g_dis[r0] : 0.f;
        float d1 = (r1 < m) ? g_dis[r1] : 0.f;
        #pragma unroll
        for (int j = 0; j < 4; j++) {
            int col = n0 + j * 8 + gc * 2;
            if (r0 < m)
                *(__half2*)(g_hs2 + (size_t)r0 * 64 + col) =
                    __floats2half2_rn(acc[mf][j][0] * d0, acc[mf][j][1] * d0);
            if (r1 < m)
                *(__half2*)(g_hs2 + (size_t)r1 * 64 + col) =
                    __floats2half2_rn(acc[mf][j][2] * d1, acc[mf][j][3] * d1);
        }
    }
}

// -------------------- Aggregation 1: x2 = relu(dis*(hs1[v]+sum)+b1) --------
// warp per node; fp16 rows (256B/warp gather), fp32 accumulation, 2-way unroll.
__global__ void k_agg1(const float* __restrict__ b1, int n) {
    int v = (blockIdx.x * blockDim.x + threadIdx.x) >> 5;
    if (v >= n) return;
    int lane = threadIdx.x & 31;
    int c = lane * 4;
    int s0 = g_rowptr[v], s1 = g_rowptr[v + 1];

    uint2 us = *(const uint2*)(g_hs1 + (size_t)v * 128 + c);   // self term
    float2 f01 = __half22float2(*(__half2*)&us.x);
    float2 f23 = __half22float2(*(__half2*)&us.y);
    float4 accA = make_float4(f01.x, f01.y, f23.x, f23.y);
    float4 accB = make_float4(0.f, 0.f, 0.f, 0.f);

    for (int j = s0; j < s1; j += 32) {
        int mm = s1 - j; if (mm > 32) mm = 32;
        int sv = (lane < mm) ? g_csr[j + lane] : 0;
        int t = 0;
        for (; t + 1 < mm; t += 2) {
            int sA = __shfl_sync(0xffffffffu, sv, t);
            int sB = __shfl_sync(0xffffffffu, sv, t + 1);
            uint2 ua = *(const uint2*)(g_hs1 + (size_t)sA * 128 + c);
            uint2 ub = *(const uint2*)(g_hs1 + (size_t)sB * 128 + c);
            float2 a01 = __half22float2(*(__half2*)&ua.x);
            float2 a23 = __half22float2(*(__half2*)&ua.y);
            float2 b01 = __half22float2(*(__half2*)&ub.x);
            float2 b23 = __half22float2(*(__half2*)&ub.y);
            accA.x += a01.x; accA.y += a01.y; accA.z += a23.x; accA.w += a23.y;
            accB.x += b01.x; accB.y += b01.y; accB.z += b23.x; accB.w += b23.y;
        }
        if (t < mm) {
            int sA = __shfl_sync(0xffffffffu, sv, t);
            uint2 ua = *(const uint2*)(g_hs1 + (size_t)sA * 128 + c);
            float2 a01 = __half22float2(*(__half2*)&ua.x);
            float2 a23 = __half22float2(*(__half2*)&ua.y);
            accA.x += a01.x; accA.y += a01.y; accA.z += a23.x; accA.w += a23.y;
        }
    }
    float dv = g_dis[v];
    float4 bb = *(const float4*)(b1 + c);
    float4 o;
    o.x = fmaxf(fmaf(dv, accA.x + accB.x, bb.x), 0.f);
    o.y = fmaxf(fmaf(dv, accA.y + accB.y, bb.y), 0.f);
    o.z = fmaxf(fmaf(dv, accA.z + accB.z, bb.z), 0.f);
    o.w = fmaxf(fmaf(dv, accA.w + accB.w, bb.w), 0.f);
    *(float4*)(g_x2 + (size_t)v * 128 + c) = o;
}

// -------------------- Aggregation 2: out = dis*(hs2[v]+sum)+b2 -------------
__global__ void k_agg2(const float* __restrict__ b2, float* __restrict__ out, int n) {
    int v = (blockIdx.x * blockDim.x + threadIdx.x) >> 5;
    if (v >= n) return;
    int lane = threadIdx.x & 31;
    int c = lane * 2;
    int s0 = g_rowptr[v], s1 = g_rowptr[v + 1];

    float2 accA = __half22float2(*(const __half2*)(g_hs2 + (size_t)v * 64 + c));
    float2 accB = make_float2(0.f, 0.f);

    for (int j = s0; j < s1; j += 32) {
        int mm = s1 - j; if (mm > 32) mm = 32;
        int sv = (lane < mm) ? g_csr[j + lane] : 0;
        int t = 0;
        for (; t + 1 < mm; t += 2) {
            int sA = __shfl_sync(0xffffffffu, sv, t);
            int sB = __shfl_sync(0xffffffffu, sv, t + 1);
            float2 ha = __half22float2(*(const __half2*)(g_hs2 + (size_t)sA * 64 + c));
            float2 hb = __half22float2(*(const __half2*)(g_hs2 + (size_t)sB * 64 + c));
            accA.x += ha.x; accA.y += ha.y;
            accB.x += hb.x; accB.y += hb.y;
        }
        if (t < mm) {
            int sA = __shfl_sync(0xffffffffu, sv, t);
            float2 ha = __half22float2(*(const __half2*)(g_hs2 + (size_t)sA * 64 + c));
            accA.x += ha.x; accA.y += ha.y;
        }
    }
    float dv = g_dis[v];
    float2 bb = *(const float2*)(b2 + c);
    float2 o;
    o.x = fmaf(dv, accA.x + accB.x, bb.x);
    o.y = fmaf(dv, accA.y + accB.y, bb.y);
    *(float2*)(out + (size_t)v * 64 + c) = o;
}

// -------------------- launch ------------------------------------------------
extern "C" void kernel_launch(void* const* d_in, const int* in_sizes, int n_in,
                              void* d_out, int out_size) {
    const float* x  = (const float*)d_in[0];
    const int*   ei = (const int*)d_in[1];
    const float* W1 = (const float*)d_in[2];
    const float* b1 = (const float*)d_in[3];
    const float* W2 = (const float*)d_in[4];
    const float* b2 = (const float*)d_in[5];
    float* out = (float*)d_out;

    const int n = in_sizes[0] / INC;   // 100000
    const int e = in_sizes[1] / 2;     // 1600000
    const int* src = ei;
    const int* dst = ei + e;

    const int nb_n = (n + 255) / 256;  // 391

    static bool attr_done = false;
    if (!attr_done) {
        cudaFuncSetAttribute(k_gemm1_mma,
                             cudaFuncAttributeMaxDynamicSharedMemorySize, G1_SMEM);
        cudaFuncSetAttribute(k_gemm2_mma,
                             cudaFuncAttributeMaxDynamicSharedMemorySize, G2_SMEM);
        attr_done = true;
    }

    // CSR build + normalization (single fused kernel, software grid barrier)
    k_csr<<<nb_n, 256>>>(src, dst, n, e, nb_n);

    // Layer 1
    k_gemm1_mma<<<(n + 127) / 128, 256, G1_SMEM>>>(x, W1, n);
    k_agg1<<<(n + 7) / 8, 256>>>(b1, n);

    // Layer 2
    k_gemm2_mma<<<(n + 127) / 128, 256, G2_SMEM>>>(W2, n);
    k_agg2<<<(n + 7) / 8, 256>>>(b2, out, n);
}

// round 9
// speedup vs baseline: 1.6260x; 1.2045x over previous
#include <cuda_runtime.h>
#include <cuda_fp16.h>
#include <cstdint>

// ---------------------------------------------------------------------------
// 2-layer GCN:  out = gcn(relu(gcn(x, W1, b1)), W2, b2)
// gcn(x,W,b)[v] = dis[v] * ( hs[v] + sum_{e: src->v} hs[src] ) + b
//   hs = (x @ W) * dis[row],  dis[v] = rsqrt(1 + indeg(v))
// GEMMs: fp16 mma.sync m16n8k16, fp32 accumulate (fp16 mantissa == tf32
// mantissa, so same error as tf32 path but half the smem/LDS/instructions).
// hs and x2 buffers stored fp16. Aggregation: pull-based CSR gather.
// ---------------------------------------------------------------------------

#define NNODES 100000
#define NEDGES 1600000
#define INC 128
#define HIDC 128
#define OUTC 64

// -------------------- scratch (device globals; no runtime alloc) -----------
__device__ int    g_cnt[NNODES];
__device__ int    g_cursor[NNODES];
__device__ int    g_rowptr[NNODES + 1];
__device__ int    g_partial[1024];
__device__ int    g_csr[NEDGES];
__device__ float  g_dis[NNODES];
__device__ __half g_hs1[(size_t)NNODES * HIDC];  // (x@W1)*dis
__device__ __half g_x2 [(size_t)NNODES * HIDC];  // relu(layer1 out)
__device__ __half g_hs2[(size_t)NNODES * OUTC];  // (x2@W2)*dis

// -------------------- mma helper --------------------------------------------
__device__ __forceinline__ void mma_f16(float* c, const uint32_t* a,
                                        uint32_t b0, uint32_t b1) {
    asm volatile(
        "mma.sync.aligned.m16n8k16.row.col.f32.f16.f16.f32 "
        "{%0,%1,%2,%3}, {%4,%5,%6,%7}, {%8,%9}, {%0,%1,%2,%3};"
        : "+f"(c[0]), "+f"(c[1]), "+f"(c[2]), "+f"(c[3])
        : "r"(a[0]), "r"(a[1]), "r"(a[2]), "r"(a[3]), "r"(b0), "r"(b1));
}

// -------------------- CSR build (7 small kernels — known good) --------------
__global__ void k_init(int n) {
    int v = blockIdx.x * blockDim.x + threadIdx.x;
    if (v < n) { g_cnt[v] = 0; g_cursor[v] = 0; }
}

__global__ void k_count(const int* __restrict__ dst, int e) {
    int i = blockIdx.x * blockDim.x + threadIdx.x;
    if (i < e) atomicAdd(&g_cnt[dst[i]], 1);
}

__global__ void k_dis(int n) {
    int v = blockIdx.x * blockDim.x + threadIdx.x;
    if (v < n) g_dis[v] = rsqrtf((float)(g_cnt[v] + 1));
}

__global__ void k_scan_blocks(int n) {
    __shared__ int warpsum[8];
    int idx  = blockIdx.x * 256 + threadIdx.x;
    int lane = threadIdx.x & 31;
    int w    = threadIdx.x >> 5;
    int x    = (idx < n) ? g_cnt[idx] : 0;
    int incl = x;
    #pragma unroll
    for (int o = 1; o < 32; o <<= 1) {
        int t = __shfl_up_sync(0xffffffffu, incl, o);
        if (lane >= o) incl += t;
    }
    if (lane == 31) warpsum[w] = incl;
    __syncthreads();
    if (w == 0) {
        int s = (lane < 8) ? warpsum[lane] : 0;
        #pragma unroll
        for (int o = 1; o < 8; o <<= 1) {
            int t = __shfl_up_sync(0xffffffffu, s, o);
            if (lane >= o) s += t;
        }
        if (lane < 8) warpsum[lane] = s;
    }
    __syncthreads();
    if (w > 0) incl += warpsum[w - 1];
    if (idx < n) g_rowptr[idx] = incl - x;
    if (threadIdx.x == 255) g_partial[blockIdx.x] = incl;
}

__global__ void k_scan_partials(int nb, int n) {
    __shared__ int warpsum[16];
    int tid  = threadIdx.x;
    int lane = tid & 31;
    int w    = tid >> 5;
    int x    = (tid < nb) ? g_partial[tid] : 0;
    int incl = x;
    #pragma unroll
    for (int o = 1; o < 32; o <<= 1) {
        int t = __shfl_up_sync(0xffffffffu, incl, o);
        if (lane >= o) incl += t;
    }
    if (lane == 31) warpsum[w] = incl;
    __syncthreads();
    if (w == 0) {
        int s = (lane < 16) ? warpsum[lane] : 0;
        #pragma unroll
        for (int o = 1; o < 16; o <<= 1) {
            int t = __shfl_up_sync(0xffffffffu, s, o);
            if (lane >= o) s += t;
        }
        if (lane < 16) warpsum[lane] = s;
    }
    __syncthreads();
    if (w > 0) incl += warpsum[w - 1];
    if (tid < nb) g_partial[tid] = incl - x;
    if (tid == nb - 1) g_rowptr[n] = incl;
}

__global__ void k_add_offsets(int n) {
    int idx = blockIdx.x * 256 + threadIdx.x;
    if (idx < n) g_rowptr[idx] += g_partial[blockIdx.x];
}

__global__ void k_fill(const int* __restrict__ src, const int* __restrict__ dst, int e) {
    int i = blockIdx.x * blockDim.x + threadIdx.x;
    if (i < e) {
        int d = dst[i];
        int p = atomicAdd(&g_cursor[d], 1);
        g_csr[g_rowptr[d] + p] = src[i];
    }
}

// -------------------- GEMM 1 (fp16 mma m16n8k16): hs1 = (X@W1)*dis ---------
// CTA 128m x 128n, K=128. As [row][k] half (stride 136), Bs [n][k] half.
// 8 warps of 32m x 64n. smem = 69.6 KB -> multi-CTA residency per SM.
#define SH_STRIDE 136
#define G1_SMEM ((128 * SH_STRIDE + 128 * SH_STRIDE) * 2)

__global__ void __launch_bounds__(256)
k_gemm1_mma(const float* __restrict__ X, const float* __restrict__ W, int m) {
    extern __shared__ __half sh[];
    __half* As = sh;                       // [128][136]  row-major (k contig)
    __half* Bs = sh + 128 * SH_STRIDE;     // [128][136]  n-major  (k contig)
    const int tid  = threadIdx.x;
    const int lane = tid & 31;
    const int wid  = tid >> 5;
    const int gr   = lane >> 2;
    const int gc   = lane & 3;
    const int bm   = blockIdx.x * 128;
    const int m0   = (wid & 3) * 32;
    const int n0   = (wid >> 2) * 64;

    // A fill: X fp32 -> fp16
    #pragma unroll
    for (int i = 0; i < 16; i++) {
        int f = tid + i * 256;             // 0..4095 float4
        int r = f >> 5, c4 = (f & 31) * 4;
        float4 v = make_float4(0.f, 0.f, 0.f, 0.f);
        if (bm + r < m) v = *(const float4*)(X + (size_t)(bm + r) * 128 + c4);
        __half2* p = (__half2*)(As + r * SH_STRIDE + c4);
        p[0] = __floats2half2_rn(v.x, v.y);
        p[1] = __floats2half2_rn(v.z, v.w);
    }
    // B fill: W1 [k][n] fp32 -> Bs [n][k] fp16 (transpose)
    #pragma unroll
    for (int i = 0; i < 32; i++) {
        int f = tid + i * 256;             // 0..8191 (n, kpair)
        int nn = f & 127, kp = f >> 7;     // kp 0..63
        float w0 = W[(size_t)(2 * kp)     * 128 + nn];
        float w1 = W[(size_t)(2 * kp + 1) * 128 + nn];
        *(__half2*)(Bs + nn * SH_STRIDE + 2 * kp) = __floats2half2_rn(w0, w1);
    }
    __syncthreads();

    float acc[2][8][4];
    #pragma unroll
    for (int a = 0; a < 2; a++)
        #pragma unroll
        for (int j = 0; j < 8; j++)
            #pragma unroll
            for (int q = 0; q < 4; q++) acc[a][j][q] = 0.f;

    #pragma unroll
    for (int ks = 0; ks < 8; ks++) {       // K=16 per step
        int kb = ks * 16;
        uint32_t a[2][4];
        #pragma unroll
        for (int mf = 0; mf < 2; mf++) {
            int r = m0 + mf * 16 + gr;
            const __half* pr0 = As + (size_t)r * SH_STRIDE + kb + 2 * gc;
            const __half* pr1 = As + (size_t)(r + 8) * SH_STRIDE + kb + 2 * gc;
            a[mf][0] = *(const uint32_t*)(pr0);
            a[mf][1] = *(const uint32_t*)(pr1);
            a[mf][2] = *(const uint32_t*)(pr0 + 8);
            a[mf][3] = *(const uint32_t*)(pr1 + 8);
        }
        #pragma unroll
        for (int j = 0; j < 8; j++) {
            int nn = n0 + j * 8 + gr;
            const __half* pb = Bs + (size_t)nn * SH_STRIDE + kb + 2 * gc;
            uint32_t b0 = *(const uint32_t*)(pb);
            uint32_t b1 = *(const uint32_t*)(pb + 8);
            mma_f16(acc[0][j], a[0], b0, b1);
            mma_f16(acc[1][j], a[1], b0, b1);
        }
    }

    // epilogue: *dis, write hs1 fp16
    #pragma unroll
    for (int mf = 0; mf < 2; mf++) {
        int r0 = bm + m0 + mf * 16 + gr;
        int r1 = r0 + 8;
        float d0 = (r0 < m) ? g_dis[r0] : 0.f;
        float d1 = (r1 < m) ? g_dis[r1] : 0.f;
        #pragma unroll
        for (int j = 0; j < 8; j++) {
            int col = n0 + j * 8 + gc * 2;
            if (r0 < m)
                *(__half2*)(g_hs1 + (size_t)r0 * 128 + col) =
                    __floats2half2_rn(acc[mf][j][0] * d0, acc[mf][j][1] * d0);
            if (r1 < m)
                *(__half2*)(g_hs1 + (size_t)r1 * 128 + col) =
                    __floats2half2_rn(acc[mf][j][2] * d1, acc[mf][j][3] * d1);
        }
    }
}

// -------------------- GEMM 2 (fp16 mma m16n8k16): hs2 = (x2@W2)*dis --------
// CTA 128m x 64n. As copied raw from fp16 x2. 8 warps of 32m x 32n. 52 KB smem.
#define G2_SMEM ((128 * SH_STRIDE + 64 * SH_STRIDE) * 2)

__global__ void __launch_bounds__(256)
k_gemm2_mma(const float* __restrict__ W, int m) {
    extern __shared__ __half sh[];
    __half* As = sh;                       // [128][136]
    __half* Bs = sh + 128 * SH_STRIDE;     // [64][136]  n-major
    const int tid  = threadIdx.x;
    const int lane = tid & 31;
    const int wid  = tid >> 5;
    const int gr   = lane >> 2;
    const int gc   = lane & 3;
    const int bm   = blockIdx.x * 128;
    const int m0   = (wid & 3) * 32;
    const int n0   = (wid >> 2) * 32;

    // A fill: raw uint4 copy of fp16 x2 rows
    #pragma unroll
    for (int i = 0; i < 8; i++) {
        int f = tid + i * 256;             // 0..2047 uint4 (8 halves)
        int r = f >> 4, c8 = (f & 15) * 8;
        uint4 v = make_uint4(0u, 0u, 0u, 0u);
        if (bm + r < m) v = *(const uint4*)(g_x2 + (size_t)(bm + r) * 128 + c8);
        *(uint4*)(As + r * SH_STRIDE + c8) = v;
    }
    // B fill: W2 [k][n] fp32 -> Bs [n][k] fp16 (transpose)
    #pragma unroll
    for (int i = 0; i < 16; i++) {
        int f = tid + i * 256;             // 0..4095 (n, kpair)
        int nn = f & 63, kp = f >> 6;      // kp 0..63
        float w0 = W[(size_t)(2 * kp)     * 64 + nn];
        float w1 = W[(size_t)(2 * kp + 1) * 64 + nn];
        *(__half2*)(Bs + nn * SH_STRIDE + 2 * kp) = __floats2half2_rn(w0, w1);
    }
    __syncthreads();

    float acc[2][4][4];
    #pragma unroll
    for (int a = 0; a < 2; a++)
        #pragma unroll
        for (int j = 0; j < 4; j++)
            #pragma unroll
            for (int q = 0; q < 4; q++) acc[a][j][q] = 0.f;

    #pragma unroll
    for (int ks = 0; ks < 8; ks++) {
        int kb = ks * 16;
        uint32_t a[2][4];
        #pragma unroll
        for (int mf = 0; mf < 2; mf++) {
            int r = m0 + mf * 16 + gr;
            const __half* pr0 = As + (size_t)r * SH_STRIDE + kb + 2 * gc;
            const __half* pr1 = As + (size_t)(r + 8) * SH_STRIDE + kb + 2 * gc;
            a[mf][0] = *(const uint32_t*)(pr0);
            a[mf][1] = *(const uint32_t*)(pr1);
            a[mf][2] = *(const uint32_t*)(pr0 + 8);
            a[mf][3] = *(const uint32_t*)(pr1 + 8);
        }
        #pragma unroll
        for (int j = 0; j < 4; j++) {
            int nn = n0 + j * 8 + gr;
            const __half* pb = Bs + (size_t)nn * SH_STRIDE + kb + 2 * gc;
            uint32_t b0 = *(const uint32_t*)(pb);
            uint32_t b1 = *(const uint32_t*)(pb + 8);
            mma_f16(acc[0][j], a[0], b0, b1);
            mma_f16(acc[1][j], a[1], b0, b1);
        }
    }

    #pragma unroll
    for (int mf = 0; mf < 2; mf++) {
        int r0 = bm + m0 + mf * 16 + gr;
        int r1 = r0 + 8;
        float d0 = (r0 < m) ? g_dis[r0] : 0.f;
        float d1 = (r1 < m) ? g_dis[r1] : 0.f;
        #pragma unroll
        for (int j = 0; j < 4; j++) {
            int col = n0 + j * 8 + gc * 2;
            if (r0 < m)
                *(__half2*)(g_hs2 + (size_t)r0 * 64 + col) =
                    __floats2half2_rn(acc[mf][j][0] * d0, acc[mf][j][1] * d0);
            if (r1 < m)
                *(__half2*)(g_hs2 + (size_t)r1 * 64 + col) =
                    __floats2half2_rn(acc[mf][j][2] * d1, acc[mf][j][3] * d1);
        }
    }
}

// -------------------- Aggregation 1: x2 = relu(dis*(hs1[v]+sum)+b1) --------
// warp per node; fp16 rows (256B/warp gather), fp32 accumulation, 2-way unroll.
__global__ void k_agg1(const float* __restrict__ b1, int n) {
    int v = (blockIdx.x * blockDim.x + threadIdx.x) >> 5;
    if (v >= n) return;
    int lane = threadIdx.x & 31;
    int c = lane * 4;
    int s0 = g_rowptr[v], s1 = g_rowptr[v + 1];

    uint2 us = *(const uint2*)(g_hs1 + (size_t)v * 128 + c);   // self term
    float2 f01 = __half22float2(*(__half2*)&us.x);
    float2 f23 = __half22float2(*(__half2*)&us.y);
    float4 accA = make_float4(f01.x, f01.y, f23.x, f23.y);
    float4 accB = make_float4(0.f, 0.f, 0.f, 0.f);

    for (int j = s0; j < s1; j += 32) {
        int mm = s1 - j; if (mm > 32) mm = 32;
        int sv = (lane < mm) ? g_csr[j + lane] : 0;
        int t = 0;
        for (; t + 1 < mm; t += 2) {
            int sA = __shfl_sync(0xffffffffu, sv, t);
            int sB = __shfl_sync(0xffffffffu, sv, t + 1);
            uint2 ua = *(const uint2*)(g_hs1 + (size_t)sA * 128 + c);
            uint2 ub = *(const uint2*)(g_hs1 + (size_t)sB * 128 + c);
            float2 a01 = __half22float2(*(__half2*)&ua.x);
            float2 a23 = __half22float2(*(__half2*)&ua.y);
            float2 b01 = __half22float2(*(__half2*)&ub.x);
            float2 b23 = __half22float2(*(__half2*)&ub.y);
            accA.x += a01.x; accA.y += a01.y; accA.z += a23.x; accA.w += a23.y;
            accB.x += b01.x; accB.y += b01.y; accB.z += b23.x; accB.w += b23.y;
        }
        if (t < mm) {
            int sA = __shfl_sync(0xffffffffu, sv, t);
            uint2 ua = *(const uint2*)(g_hs1 + (size_t)sA * 128 + c);
            float2 a01 = __half22float2(*(__half2*)&ua.x);
            float2 a23 = __half22float2(*(__half2*)&ua.y);
            accA.x += a01.x; accA.y += a01.y; accA.z += a23.x; accA.w += a23.y;
        }
    }
    float dv = g_dis[v];
    float4 bb = *(const float4*)(b1 + c);
    float ox = fmaxf(fmaf(dv, accA.x + accB.x, bb.x), 0.f);
    float oy = fmaxf(fmaf(dv, accA.y + accB.y, bb.y), 0.f);
    float oz = fmaxf(fmaf(dv, accA.z + accB.z, bb.z), 0.f);
    float ow = fmaxf(fmaf(dv, accA.w + accB.w, bb.w), 0.f);
    __half2 h01 = __floats2half2_rn(ox, oy);
    __half2 h23 = __floats2half2_rn(oz, ow);
    uint2 pk;
    pk.x = *(uint32_t*)&h01;
    pk.y = *(uint32_t*)&h23;
    *(uint2*)(g_x2 + (size_t)v * 128 + c) = pk;
}

// -------------------- Aggregation 2: out = dis*(hs2[v]+sum)+b2 -------------
__global__ void k_agg2(const float* __restrict__ b2, float* __restrict__ out, int n) {
    int v = (blockIdx.x * blockDim.x + threadIdx.x) >> 5;
    if (v >= n) return;
    int lane = threadIdx.x & 31;
    int c = lane * 2;
    int s0 = g_rowptr[v], s1 = g_rowptr[v + 1];

    float2 accA = __half22float2(*(const __half2*)(g_hs2 + (size_t)v * 64 + c));
    float2 accB = make_float2(0.f, 0.f);

    for (int j = s0; j < s1; j += 32) {
        int mm = s1 - j; if (mm > 32) mm = 32;
        int sv = (lane < mm) ? g_csr[j + lane] : 0;
        int t = 0;
        for (; t + 1 < mm; t += 2) {
            int sA = __shfl_sync(0xffffffffu, sv, t);
            int sB = __shfl_sync(0xffffffffu, sv, t + 1);
            float2 ha = __half22float2(*(const __half2*)(g_hs2 + (size_t)sA * 64 + c));
            float2 hb = __half22float2(*(const __half2*)(g_hs2 + (size_t)sB * 64 + c));
            accA.x += ha.x; accA.y += ha.y;
            accB.x += hb.x; accB.y += hb.y;
        }
        if (t < mm) {
            int sA = __shfl_sync(0xffffffffu, sv, t);
            float2 ha = __half22float2(*(const __half2*)(g_hs2 + (size_t)sA * 64 + c));
            accA.x += ha.x; accA.y += ha.y;
        }
    }
    float dv = g_dis[v];
    float2 bb = *(const float2*)(b2 + c);
    float2 o;
    o.x = fmaf(dv, accA.x + accB.x, bb.x);
    o.y = fmaf(dv, accA.y + accB.y, bb.y);
    *(float2*)(out + (size_t)v * 64 + c) = o;
}

// -------------------- launch ------------------------------------------------
extern "C" void kernel_launch(void* const* d_in, const int* in_sizes, int n_in,
                              void* d_out, int out_size) {
    const float* x  = (const float*)d_in[0];
    const int*   ei = (const int*)d_in[1];
    const float* W1 = (const float*)d_in[2];
    const float* b1 = (const float*)d_in[3];
    const float* W2 = (const float*)d_in[4];
    const float* b2 = (const float*)d_in[5];
    float* out = (float*)d_out;

    const int n = in_sizes[0] / INC;   // 100000
    const int e = in_sizes[1] / 2;     // 1600000
    const int* src = ei;
    const int* dst = ei + e;

    const int nb_n = (n + 255) / 256;  // 391
    const int nb_e = (e + 255) / 256;

    cudaFuncSetAttribute(k_gemm1_mma,
                         cudaFuncAttributeMaxDynamicSharedMemorySize, G1_SMEM);
    cudaFuncSetAttribute(k_gemm2_mma,
                         cudaFuncAttributeMaxDynamicSharedMemorySize, G2_SMEM);

    // CSR build + normalization
    k_init<<<nb_n, 256>>>(n);
    k_count<<<nb_e, 256>>>(dst, e);
    k_dis<<<nb_n, 256>>>(n);
    k_scan_blocks<<<nb_n, 256>>>(n);
    k_scan_partials<<<1, 512>>>(nb_n, n);
    k_add_offsets<<<nb_n, 256>>>(n);
    k_fill<<<nb_e, 256>>>(src, dst, e);

    // Layer 1
    k_gemm1_mma<<<(n + 127) / 128, 256, G1_SMEM>>>(x, W1, n);
    k_agg1<<<(n + 7) / 8, 256>>>(b1, n);

    // Layer 2
    k_gemm2_mma<<<(n + 127) / 128, 256, G2_SMEM>>>(W2, n);
    k_agg2<<<(n + 7) / 8, 256>>>(b2, out, n);
}